// round 4
// baseline (speedup 1.0000x reference)
#include <cuda_runtime.h>
#include <cuda_bf16.h>

#define HWT 32768   // 32*32*32 positions
#define NHEAD 16
#define HD 64

// Scratch: Q/K in layout [head][dchunk][pos] of float4 (4 consecutive head-dims).
// plane index = n*16 + dc, each plane HWT float4s. 134 MB each.
__device__ float4 g_Q4[NHEAD * 16 * HWT];
__device__ float4 g_K4[NHEAD * 16 * HWT];

__device__ __forceinline__ void ffma2(unsigned long long& acc,
                                      unsigned long long a,
                                      unsigned long long b) {
    asm("fma.rn.f32x2 %0, %1, %2, %0;" : "+l"(acc) : "l"(a), "l"(b));
}
__device__ __forceinline__ unsigned long long splat2(float v) {
    unsigned long long r;
    asm("mov.b64 %0, {%1, %1};" : "=l"(r) : "f"(v));
    return r;
}
__device__ __forceinline__ float2 unpack2(unsigned long long v) {
    float2 r;
    asm("mov.b64 {%0, %1}, %2;" : "=f"(r.x), "=f"(r.y) : "l"(v));
    return r;
}

// ---------------------------------------------------------------------------
// Kernel 1: fused LayerNorm + Linear projection.
// Block tile: 64 positions x 128 output channels. 256 threads.
// blockIdx.z = 0 -> F path (writes g_Q4), 1 -> M path (writes g_K4).
// A stored LN'd in smem [k][pos]; inner loop uses packed f32x2 FMA over
// position pairs (a-pair from smem float2, b splatted).
// ---------------------------------------------------------------------------
__global__ __launch_bounds__(256) void proj_kernel(
    const float* __restrict__ F,  const float* __restrict__ gf,
    const float* __restrict__ bf, const float* __restrict__ wf,
    const float* __restrict__ biasf,
    const float* __restrict__ M,  const float* __restrict__ gm,
    const float* __restrict__ bm, const float* __restrict__ wm,
    const float* __restrict__ biasm)
{
    __shared__ float As[64][64];    // [cin][pos], LN'd in place
    __shared__ float Ws[64][128];   // [cin][cout_local]

    const float* X;  const float* gamma; const float* beta;
    const float* W;  const float* bias;  float4* out;
    if (blockIdx.z == 0) { X = F; gamma = gf; beta = bf; W = wf; bias = biasf; out = g_Q4; }
    else                 { X = M; gamma = gm; beta = bm; W = wm; bias = biasm; out = g_K4; }

    int tid = threadIdx.x;
    int p0  = blockIdx.x * 64;
    int c0  = blockIdx.y * 128;

    // load A tile (raw), coalesced: pl fastest
    {
        int pl = tid & 63, cr = tid >> 6;
        #pragma unroll
        for (int it = 0; it < 16; it++) {
            int c = cr + it * 4;
            As[c][pl] = X[c * HWT + p0 + pl];
        }
    }
    // load W tile, coalesced
    {
        #pragma unroll
        for (int it = 0; it < 32; it++) {
            int i = tid + it * 256;
            int k = i >> 7, j = i & 127;
            Ws[k][j] = W[k * 1024 + c0 + j];
        }
    }
    __syncthreads();

    // LayerNorm per position (threads 0..63, one position each; column reads
    // As[c][tid] are conflict-free across lanes)
    if (tid < 64) {
        float s = 0.f, ss = 0.f;
        #pragma unroll
        for (int c = 0; c < 64; c++) { float v = As[c][tid]; s += v; ss += v * v; }
        float mu  = s * (1.f / 64.f);
        float var = ss * (1.f / 64.f) - mu * mu;
        float inv = rsqrtf(var + 1e-5f);
        #pragma unroll
        for (int c = 0; c < 64; c++)
            As[c][tid] = (As[c][tid] - mu) * inv * gamma[c] + beta[c];
    }
    __syncthreads();

    // GEMM: thread = (tp, tc); tp = warp id (broadcast a-loads),
    // tc = lane (coalesced float4 b-loads). 8 positions x 4 couts per thread.
    int tc = tid & 31;
    int tp = tid >> 5;

    unsigned long long acc[4][4];
    #pragma unroll
    for (int i = 0; i < 4; i++)
        #pragma unroll
        for (int j = 0; j < 4; j++) acc[i][j] = 0ull;

    #pragma unroll 4
    for (int k = 0; k < 64; k++) {
        float4 bv = *(const float4*)&Ws[k][tc * 4];
        unsigned long long b0 = splat2(bv.x), b1 = splat2(bv.y),
                           b2 = splat2(bv.z), b3 = splat2(bv.w);
        const float* ar = &As[k][tp * 8];
        unsigned long long a0 = *(const unsigned long long*)(ar + 0);
        unsigned long long a1 = *(const unsigned long long*)(ar + 2);
        unsigned long long a2 = *(const unsigned long long*)(ar + 4);
        unsigned long long a3 = *(const unsigned long long*)(ar + 6);
        ffma2(acc[0][0], a0, b0); ffma2(acc[0][1], a0, b1);
        ffma2(acc[0][2], a0, b2); ffma2(acc[0][3], a0, b3);
        ffma2(acc[1][0], a1, b0); ffma2(acc[1][1], a1, b1);
        ffma2(acc[1][2], a1, b2); ffma2(acc[1][3], a1, b3);
        ffma2(acc[2][0], a2, b0); ffma2(acc[2][1], a2, b1);
        ffma2(acc[2][2], a2, b2); ffma2(acc[2][3], a2, b3);
        ffma2(acc[3][0], a3, b0); ffma2(acc[3][1], a3, b1);
        ffma2(acc[3][2], a3, b2); ffma2(acc[3][3], a3, b3);
    }

    // Epilogue: bias + store. Thread's 4 couts form one float4 (j=0..3) in
    // plane (n, dc); 8 consecutive positions -> this thread fills a 128B line.
    int cb = c0 + tc * 4;
    float4 bb = *(const float4*)&bias[cb];
    int plane = ((cb >> 6) << 4) + ((cb >> 2) & 15);   // n*16 + dc
    float4* op = out + (size_t)plane * HWT + p0 + tp * 8;
    #pragma unroll
    for (int i = 0; i < 4; i++) {
        float2 r0 = unpack2(acc[i][0]);
        float2 r1 = unpack2(acc[i][1]);
        float2 r2 = unpack2(acc[i][2]);
        float2 r3 = unpack2(acc[i][3]);
        float4 lo = make_float4(r0.x + bb.x, r1.x + bb.y, r2.x + bb.z, r3.x + bb.w);
        float4 hi = make_float4(r0.y + bb.x, r1.y + bb.y, r2.y + bb.z, r3.y + bb.w);
        op[2 * i]     = lo;
        op[2 * i + 1] = hi;
    }
}

// ---------------------------------------------------------------------------
// Kernel 2: 3x3x3 neighborhood attention + softmax + V_GRID contraction.
// Block: one head x 4x4x32 position tile, 512 threads (1 pos/thread).
// Per dchunk (float4 of 4 head-dims): stage haloed K tile 6x6x34 in smem,
// each thread accumulates 27 scores via LDS.128 (conflict-free: lanes span t).
// Zero-padding of K at boundaries -> boundary scores = 0 + rpb (in softmax).
// ---------------------------------------------------------------------------
__global__ __launch_bounds__(512) void attn_kernel(
    const float* __restrict__ rpb, float* __restrict__ out)
{
    __shared__ float4 sk[6 * 6 * 34];   // 1224 float4 = 19.6 KB
    __shared__ float  srpb[27];

    int tid = threadIdx.x;
    int n   = blockIdx.y;
    int hT  = blockIdx.x >> 3, wT = blockIdx.x & 7;
    int h0  = hT * 4, w0 = wT * 4;

    int x = tid & 31;            // t (lane-contiguous -> coalesced/conflict-free)
    int y = (tid >> 5) & 3;      // w
    int z = tid >> 7;            // h
    int h = h0 + z, w = w0 + y, t = x;
    int p = h * 1024 + w * 32 + t;

    if (tid < 27) srpb[tid] = rpb[n * 27 + tid];

    float sc[27];
    #pragma unroll
    for (int o = 0; o < 27; o++) sc[o] = 0.f;

    int center = ((z + 1) * 6 + (y + 1)) * 34 + (x + 1);
    const float4* Qb = g_Q4 + (size_t)(n * 16) * HWT;
    const float4* Kb = g_K4 + (size_t)(n * 16) * HWT;

    #pragma unroll 1
    for (int dc = 0; dc < 16; dc++) {
        __syncthreads();
        const float4* Kp = Kb + (size_t)dc * HWT;
        for (int i = tid; i < 1224; i += 512) {
            int hz = i / 204;  int r = i - hz * 204;
            int hy = r / 34;   int hx = r - hy * 34;
            int gz = h0 + hz - 1, gy = w0 + hy - 1, gx = hx - 1;
            float4 v = make_float4(0.f, 0.f, 0.f, 0.f);
            if ((unsigned)gz < 32u && (unsigned)gy < 32u && (unsigned)gx < 32u)
                v = Kp[gz * 1024 + gy * 32 + gx];
            sk[i] = v;
        }
        __syncthreads();

        float4 q = Qb[(size_t)dc * HWT + p];
        #pragma unroll
        for (int dz = 0; dz < 3; dz++)
            #pragma unroll
            for (int dy = 0; dy < 3; dy++)
                #pragma unroll
                for (int dx = 0; dx < 3; dx++) {
                    int o = (dz * 3 + dy) * 3 + dx;
                    float4 kv = sk[center + (dz - 1) * 204 + (dy - 1) * 34 + (dx - 1)];
                    sc[o] += q.x * kv.x + q.y * kv.y + q.z * kv.z + q.w * kv.w;
                }
    }

    // add rpb, softmax, contract with V_GRID = (dz-1, dy-1, dx-1)
    float m = -1e30f;
    #pragma unroll
    for (int o = 0; o < 27; o++) { sc[o] += srpb[o]; m = fmaxf(m, sc[o]); }
    float se = 0.f, s0 = 0.f, s1 = 0.f, s2 = 0.f;
    #pragma unroll
    for (int o = 0; o < 27; o++) {
        float e = __expf(sc[o] - m);
        se += e;
        s0 += e * (float)(o / 9 - 1);
        s1 += e * (float)((o / 3) % 3 - 1);
        s2 += e * (float)(o % 3 - 1);
    }
    float inv = 1.f / se;
    out[(n * 3 + 0) * HWT + p] = s0 * inv;
    out[(n * 3 + 1) * HWT + p] = s1 * inv;
    out[(n * 3 + 2) * HWT + p] = s2 * inv;
}

extern "C" void kernel_launch(void* const* d_in, const int* in_sizes, int n_in,
                              void* d_out, int out_size) {
    const float* F       = (const float*)d_in[0];
    const float* M       = (const float*)d_in[1];
    const float* gamma_f = (const float*)d_in[2];
    const float* beta_f  = (const float*)d_in[3];
    const float* w_f     = (const float*)d_in[4];
    const float* b_f     = (const float*)d_in[5];
    const float* gamma_m = (const float*)d_in[6];
    const float* beta_m  = (const float*)d_in[7];
    const float* w_m     = (const float*)d_in[8];
    const float* b_m     = (const float*)d_in[9];
    const float* rpb     = (const float*)d_in[10];
    float* out = (float*)d_out;

    dim3 pgrid(HWT / 64, 1024 / 128, 2);
    proj_kernel<<<pgrid, 256>>>(F, gamma_f, beta_f, w_f, b_f,
                                M, gamma_m, beta_m, w_m, b_m);

    dim3 agrid(64, NHEAD);
    attn_kernel<<<agrid, 512>>>(rpb, out);
}

// round 6
// speedup vs baseline: 1.2788x; 1.2788x over previous
#include <cuda_runtime.h>
#include <cuda_bf16.h>

#define HWT 32768   // 32*32*32 positions
#define NHEAD 16

// Scratch: Q/K in layout [head][dchunk][pos] of float4 (4 consecutive head-dims).
__device__ float4 g_Q4[NHEAD * 16 * HWT];
__device__ float4 g_K4[NHEAD * 16 * HWT];

__device__ __forceinline__ void ffma2(unsigned long long& acc,
                                      unsigned long long a,
                                      unsigned long long b) {
    asm("fma.rn.f32x2 %0, %1, %2, %0;" : "+l"(acc) : "l"(a), "l"(b));
}
__device__ __forceinline__ unsigned long long splat2(float v) {
    unsigned long long r;
    asm("mov.b64 %0, {%1, %1};" : "=l"(r) : "f"(v));
    return r;
}
__device__ __forceinline__ float2 unpack2(unsigned long long v) {
    float2 r;
    asm("mov.b64 {%0, %1}, %2;" : "=f"(r.x), "=f"(r.y) : "l"(v));
    return r;
}

// ---------------------------------------------------------------------------
// Kernel 1: fused LayerNorm + Linear projection.
// Block: 128 threads, tile 64 positions x 256 output channels.
// Per-thread: 8 positions (4 f32x2 pairs) x 16 couts -> 64 FFMA2 per k for
// 96B smem -> fma-pipe bound. Ws stored interleaved [(k,jg)][tc] (pad 17)
// so b-reads are 16B-stride conflict-free LDS.128.
// blockIdx.z = 0 -> F path (writes g_Q4), 1 -> M path (writes g_K4).
// ---------------------------------------------------------------------------
__global__ __launch_bounds__(128) void proj_kernel(
    const float* __restrict__ F,  const float* __restrict__ gf,
    const float* __restrict__ bf, const float* __restrict__ wf,
    const float* __restrict__ biasf,
    const float* __restrict__ M,  const float* __restrict__ gm,
    const float* __restrict__ bm, const float* __restrict__ wm,
    const float* __restrict__ biasm)
{
    extern __shared__ float psm[];           // As: 64*64 floats, then Ws
    float4* Wsv = (float4*)(psm + 64 * 64);  // 4351 float4

    const float* X;  const float* gamma; const float* beta;
    const float* W;  const float* bias;  float4* out;
    if (blockIdx.z == 0) { X = F; gamma = gf; beta = bf; W = wf; bias = biasf; out = g_Q4; }
    else                 { X = M; gamma = gm; beta = bm; W = wm; bias = biasm; out = g_K4; }

    int tid = threadIdx.x;
    int p0  = blockIdx.x * 64;
    int c0  = blockIdx.y * 256;

    // Load A tile (64 c x 64 pos) as float4, coalesced.
    {
        #pragma unroll
        for (int it = 0; it < 8; it++) {
            int i = tid + it * 128;          // 1024 float4
            int c = i >> 4, quad = i & 15;
            *(float4*)&psm[c * 64 + quad * 4] =
                *(const float4*)&X[c * HWT + p0 + quad * 4];
        }
    }
    // Load W tile (64 k x 256 c) into interleaved layout.
    {
        #pragma unroll
        for (int it = 0; it < 32; it++) {
            int i = tid + it * 128;          // 4096 float4
            int k = i >> 6, q = i & 63;
            int tcq = q >> 2, jg = q & 3;
            Wsv[(k * 4 + jg) * 17 + tcq] =
                *(const float4*)&W[k * 1024 + c0 + q * 4];
        }
    }
    __syncthreads();

    // LayerNorm per position (threads 0..63; column reads conflict-free).
    if (tid < 64) {
        float s = 0.f, ss = 0.f;
        #pragma unroll
        for (int c = 0; c < 64; c++) { float v = psm[c * 64 + tid]; s += v; ss += v * v; }
        float mu  = s * (1.f / 64.f);
        float var = ss * (1.f / 64.f) - mu * mu;
        float inv = rsqrtf(var + 1e-5f);
        #pragma unroll
        for (int c = 0; c < 64; c++)
            psm[c * 64 + tid] = (psm[c * 64 + tid] - mu) * inv * __ldg(&gamma[c]) + __ldg(&beta[c]);
    }
    __syncthreads();

    int tc = tid & 15;          // cout group (16 couts)
    int tp = tid >> 4;          // pos group (8 positions)

    unsigned long long acc[4][16];
    #pragma unroll
    for (int i = 0; i < 4; i++)
        #pragma unroll
        for (int j = 0; j < 16; j++) acc[i][j] = 0ull;

    #pragma unroll 4
    for (int k = 0; k < 64; k++) {
        const float* ar = &psm[k * 64 + tp * 8];
        unsigned long long a0 = *(const unsigned long long*)(ar + 0);
        unsigned long long a1 = *(const unsigned long long*)(ar + 2);
        unsigned long long a2 = *(const unsigned long long*)(ar + 4);
        unsigned long long a3 = *(const unsigned long long*)(ar + 6);
        #pragma unroll
        for (int jg = 0; jg < 4; jg++) {
            float4 bv = Wsv[(k * 4 + jg) * 17 + tc];
            unsigned long long b0 = splat2(bv.x), b1 = splat2(bv.y),
                               b2 = splat2(bv.z), b3 = splat2(bv.w);
            ffma2(acc[0][jg*4+0], a0, b0); ffma2(acc[0][jg*4+1], a0, b1);
            ffma2(acc[0][jg*4+2], a0, b2); ffma2(acc[0][jg*4+3], a0, b3);
            ffma2(acc[1][jg*4+0], a1, b0); ffma2(acc[1][jg*4+1], a1, b1);
            ffma2(acc[1][jg*4+2], a1, b2); ffma2(acc[1][jg*4+3], a1, b3);
            ffma2(acc[2][jg*4+0], a2, b0); ffma2(acc[2][jg*4+1], a2, b1);
            ffma2(acc[2][jg*4+2], a2, b2); ffma2(acc[2][jg*4+3], a2, b3);
            ffma2(acc[3][jg*4+0], a3, b0); ffma2(acc[3][jg*4+1], a3, b1);
            ffma2(acc[3][jg*4+2], a3, b2); ffma2(acc[3][jg*4+3], a3, b3);
        }
    }

    // Epilogue: bias + store into plane layout.
    int cb0 = c0 + tc * 16;
    #pragma unroll
    for (int jg = 0; jg < 4; jg++) {
        int cb = cb0 + jg * 4;
        float4 bb = *(const float4*)&bias[cb];
        int plane = ((cb >> 6) << 4) | ((cb >> 2) & 15);   // n*16 + dc
        float4* op = out + (size_t)plane * HWT + p0 + tp * 8;
        #pragma unroll
        for (int pi = 0; pi < 4; pi++) {
            float2 r0 = unpack2(acc[pi][jg*4+0]);
            float2 r1 = unpack2(acc[pi][jg*4+1]);
            float2 r2 = unpack2(acc[pi][jg*4+2]);
            float2 r3 = unpack2(acc[pi][jg*4+3]);
            op[2*pi]   = make_float4(r0.x + bb.x, r1.x + bb.y, r2.x + bb.z, r3.x + bb.w);
            op[2*pi+1] = make_float4(r0.y + bb.x, r1.y + bb.y, r2.y + bb.z, r3.y + bb.w);
        }
    }
}

// ---------------------------------------------------------------------------
// Kernel 2: 3x3x3 neighborhood attention + softmax + V_GRID contraction.
// Block: one head x 4(h)x4(w)x32(t) tile, 256 threads, 2 y-adjacent
// positions per thread. Per dchunk: 3x4x3 = 36 unique K float4 loads serve
// both positions' 27 scores (1.5x LDS cut). K tile double-buffered with
// cp.async (zero-fill halo), one barrier per dc, next-q prefetched.
// ---------------------------------------------------------------------------
#define HALO_N 1224   // 6*6*34

__global__ __launch_bounds__(256) void attn_kernel(
    const float* __restrict__ rpb, float* __restrict__ out)
{
    __shared__ float4 sk[2][HALO_N];   // 2 x 19.6 KB
    __shared__ float  srpb[27];

    int tid = threadIdx.x;
    int n   = blockIdx.y;
    int hT  = blockIdx.x >> 3, wT = blockIdx.x & 7;
    int h0  = hT * 4, w0 = wT * 4;

    int x   = tid & 31;          // t
    int typ = (tid >> 5) & 1;    // y-pair
    int z   = tid >> 6;          // h (0..3)
    int y0  = typ * 2;
    int h = h0 + z;
    int pA = h * 1024 + (w0 + y0) * 32 + x;
    int pB = pA + 32;

    if (tid < 27) srpb[tid] = rpb[n * 27 + tid];

    // Precompute staging addresses (constant across dc).
    int goff[5]; unsigned ok[5];
    #pragma unroll
    for (int j = 0; j < 5; j++) {
        int i = tid + j * 256;
        goff[j] = 0; ok[j] = 0;
        if (i < HALO_N) {
            int hz = i / 204;  int r = i - hz * 204;
            int hy = r / 34;   int hx = r - hy * 34;
            int gz = h0 + hz - 1, gy = w0 + hy - 1, gx = hx - 1;
            bool v = ((unsigned)gz < 32u) & ((unsigned)gy < 32u) & ((unsigned)gx < 32u);
            goff[j] = v ? (gz * 1024 + gy * 32 + gx) : 0;
            ok[j]   = v ? 16u : 0u;
        }
    }

    const float4* Qb = g_Q4 + (size_t)(n * 16) * HWT + pA;   // +32 for B
    const float4* Kb = g_K4 + (size_t)(n * 16) * HWT;

    // Stage dc=0 into buffer 0.
    {
        const float4* Kp = Kb;
        #pragma unroll
        for (int j = 0; j < 5; j++) {
            int i = tid + j * 256;
            if (i < HALO_N) {
                unsigned sa = (unsigned)__cvta_generic_to_shared(&sk[0][i]);
                asm volatile("cp.async.cg.shared.global [%0], [%1], 16, %2;"
                             :: "r"(sa), "l"((const void*)(Kp + goff[j])), "r"(ok[j]));
            }
        }
        asm volatile("cp.async.commit_group;");
    }

    float scA[27], scB[27];
    #pragma unroll
    for (int o = 0; o < 27; o++) { scA[o] = 0.f; scB[o] = 0.f; }

    float4 qA = Qb[0];
    float4 qB = Qb[32];
    int base = (z * 6 + y0) * 34 + x;

    #pragma unroll 1
    for (int dc = 0; dc < 16; dc++) {
        asm volatile("cp.async.wait_group 0;" ::: "memory");
        __syncthreads();

        // Prefetch next K tile into the other buffer (overlaps compute).
        if (dc < 15) {
            const float4* Kp = Kb + (size_t)(dc + 1) * HWT;
            float4* buf = sk[(dc + 1) & 1];
            #pragma unroll
            for (int j = 0; j < 5; j++) {
                int i = tid + j * 256;
                if (i < HALO_N) {
                    unsigned sa = (unsigned)__cvta_generic_to_shared(&buf[i]);
                    asm volatile("cp.async.cg.shared.global [%0], [%1], 16, %2;"
                                 :: "r"(sa), "l"((const void*)(Kp + goff[j])), "r"(ok[j]));
                }
            }
            asm volatile("cp.async.commit_group;");
        }

        // Prefetch next q.
        float4 qA_n, qB_n;
        if (dc < 15) {
            qA_n = Qb[(size_t)(dc + 1) * HWT];
            qB_n = Qb[(size_t)(dc + 1) * HWT + 32];
        }

        const float4* cur = sk[dc & 1];
        #pragma unroll
        for (int dzp = 0; dzp < 3; dzp++)
            #pragma unroll
            for (int kyp = 0; kyp < 4; kyp++)
                #pragma unroll
                for (int dxp = 0; dxp < 3; dxp++) {
                    float4 kv = cur[base + (dzp * 6 + kyp) * 34 + dxp];
                    if (kyp < 3) {
                        int o = (dzp * 3 + kyp) * 3 + dxp;
                        scA[o] += qA.x * kv.x + qA.y * kv.y + qA.z * kv.z + qA.w * kv.w;
                    }
                    if (kyp > 0) {
                        int o = (dzp * 3 + (kyp - 1)) * 3 + dxp;
                        scB[o] += qB.x * kv.x + qB.y * kv.y + qB.z * kv.z + qB.w * kv.w;
                    }
                }
        qA = qA_n; qB = qB_n;
    }

    // rpb + softmax + V_GRID contraction, both positions.
    #pragma unroll
    for (int pos = 0; pos < 2; pos++) {
        float* sc = pos ? scB : scA;
        int p = pos ? pB : pA;
        float m = -1e30f;
        #pragma unroll
        for (int o = 0; o < 27; o++) { sc[o] += srpb[o]; m = fmaxf(m, sc[o]); }
        float se = 0.f, s0 = 0.f, s1 = 0.f, s2 = 0.f;
        #pragma unroll
        for (int o = 0; o < 27; o++) {
            float e = __expf(sc[o] - m);
            se += e;
            s0 += e * (float)(o / 9 - 1);
            s1 += e * (float)((o / 3) % 3 - 1);
            s2 += e * (float)(o % 3 - 1);
        }
        float inv = 1.f / se;
        out[(n * 3 + 0) * HWT + p] = s0 * inv;
        out[(n * 3 + 1) * HWT + p] = s1 * inv;
        out[(n * 3 + 2) * HWT + p] = s2 * inv;
    }
}

extern "C" void kernel_launch(void* const* d_in, const int* in_sizes, int n_in,
                              void* d_out, int out_size) {
    const float* F       = (const float*)d_in[0];
    const float* M       = (const float*)d_in[1];
    const float* gamma_f = (const float*)d_in[2];
    const float* beta_f  = (const float*)d_in[3];
    const float* w_f     = (const float*)d_in[4];
    const float* b_f     = (const float*)d_in[5];
    const float* gamma_m = (const float*)d_in[6];
    const float* beta_m  = (const float*)d_in[7];
    const float* w_m     = (const float*)d_in[8];
    const float* b_m     = (const float*)d_in[9];
    const float* rpb     = (const float*)d_in[10];
    float* out = (float*)d_out;

    const int PSMEM = (64 * 64 + 4351 * 4) * 4;   // 86000 B
    cudaFuncSetAttribute(proj_kernel, cudaFuncAttributeMaxDynamicSharedMemorySize, PSMEM);

    dim3 pgrid(HWT / 64, 1024 / 256, 2);
    proj_kernel<<<pgrid, 128, PSMEM>>>(F, gamma_f, beta_f, w_f, b_f,
                                       M, gamma_m, beta_m, w_m, b_m);

    dim3 agrid(64, NHEAD);
    attn_kernel<<<agrid, 256>>>(rpb, out);
}